// round 12
// baseline (speedup 1.0000x reference)
#include <cuda_runtime.h>
#include <cstddef>
#include <cstdint>

// Problem constants
#define BB 32
#define SS 1024
#define EE 512
#define HH 1024
#define GG 4096          // 4*H
#define DKV 512

#define NBLK 128         // persistent grid: 1 block/SM
#define NTHR 256

#define NB2 16           // batches per half-chain
#define HS2 24           // half-slab row stride (banks {0,24,16,8}+c: conflict-free)
#define RS2 18           // k-reduce row stride (even -> float2 8B-aligned)

// Scratch (device globals; no allocation allowed)
// g_xg layout: [S][B][4H]   (step-major; written by phase A with perm=1)
// g_hs layout: [S][B][H]    (step-major; phase C permutes output rows, perm=2)
__device__ __align__(16) float g_xg[(size_t)BB * SS * GG];
__device__ __align__(16) float g_hs[(size_t)BB * SS * HH];
__device__ __align__(16) float g_hT2[2][2][HH * NB2];   // [half][buf][k*16+b], tf32-rounded
__device__ unsigned int g_done2[2][SS];                 // per-half per-step counters
__device__ unsigned int g_arrive = 0;
__device__ unsigned int g_gen = 0;

// ---------------------------------------------------------------------------
// helpers
// ---------------------------------------------------------------------------
__device__ __forceinline__ uint32_t f2tf32(float f) {
    uint32_t u;
    asm("cvt.rna.tf32.f32 %0, %1;" : "=r"(u) : "f"(f));
    return u;
}

__device__ __forceinline__ void mma_tf32(float& d0, float& d1, float& d2, float& d3,
                                         uint32_t a0, uint32_t a1, uint32_t a2, uint32_t a3,
                                         uint32_t b0, uint32_t b1) {
    asm("mma.sync.aligned.m16n8k8.row.col.f32.tf32.tf32.f32 "
        "{%0,%1,%2,%3}, {%4,%5,%6,%7}, {%8,%9}, {%0,%1,%2,%3};"
        : "+f"(d0), "+f"(d1), "+f"(d2), "+f"(d3)
        : "r"(a0), "r"(a1), "r"(a2), "r"(a3), "r"(b0), "r"(b1));
}

__device__ __forceinline__ void cpa16(float* smem, const float* g) {
    uint32_t s = (uint32_t)__cvta_generic_to_shared(smem);
    asm volatile("cp.async.cg.shared.global [%0], [%1], 16;" :: "r"(s), "l"(g));
}
__device__ __forceinline__ void cpa_commit() {
    asm volatile("cp.async.commit_group;");
}
__device__ __forceinline__ void cpa_wait1() {
    asm volatile("cp.async.wait_group 1;");
}
__device__ __forceinline__ void cpa_wait0() {
    asm volatile("cp.async.wait_group 0;");
}

// ---------------------------------------------------------------------------
// tf32 tensor-core GEMM: C[M,N] = A[M,K]*W[N,K]^T + bias1 + bias2
// perm: 0 = identity; 1 = xg perm; 2 = out perm   (unchanged, passing)
// ---------------------------------------------------------------------------
__global__ void __launch_bounds__(256, 2)
gemm_tf32(const float* __restrict__ A,
          const float* __restrict__ W,
          const float* __restrict__ bias1,
          const float* __restrict__ bias2,
          float* __restrict__ C,
          int M, int N, int K, int perm) {
    extern __shared__ uint32_t gsm[];   // 2 stages x (Af 4096 + Bf 4096) u32

    const int tid  = threadIdx.x;
    const int lane = tid & 31;
    const int wid  = tid >> 5;
    const int mw   = wid >> 1;
    const int nw   = wid & 1;
    const int row0 = blockIdx.y * 128;
    const int col0 = blockIdx.x * 128;

    float4 ra[4], rb[4];

#define LDG_TILE(k0)                                                          \
    do {                                                                      \
        _Pragma("unroll")                                                     \
        for (int i = 0; i < 4; i++) {                                         \
            int v = tid + i * 256, row = v >> 3, kq = v & 7;                  \
            ra[i] = *(const float4*)&A[(size_t)(row0 + row) * K + (k0) + kq * 4]; \
        }                                                                     \
        _Pragma("unroll")                                                     \
        for (int i = 0; i < 4; i++) {                                         \
            int v = tid + i * 256, n = v >> 3, kq = v & 7;                    \
            rb[i] = *(const float4*)&W[(size_t)(col0 + n) * K + (k0) + kq * 4]; \
        }                                                                     \
    } while (0)

#define STS_TILE(stp)                                                         \
    do {                                                                      \
        uint32_t* Af = (stp);                                                 \
        uint32_t* Bf = (stp) + 4096;                                          \
        _Pragma("unroll")                                                     \
        for (int i = 0; i < 4; i++) {                                         \
            int v = tid + i * 256, row = v >> 3, kq = v & 7;                  \
            int mt = row >> 4, rw = row & 15;                                 \
            const float* pf = (const float*)&ra[i];                           \
            _Pragma("unroll")                                                 \
            for (int e = 0; e < 4; e++) {                                     \
                int kl = kq * 4 + e, ks = kl >> 3, kk = kl & 7;               \
                int ln = (rw & 7) * 4 + (kk & 3);                             \
                int r  = (rw >> 3) + 2 * (kk >> 2);                           \
                Af[((ks * 8 + mt) * 32 + ln) * 4 + r] = f2tf32(pf[e]);        \
            }                                                                 \
        }                                                                     \
        _Pragma("unroll")                                                     \
        for (int i = 0; i < 4; i++) {                                         \
            int v = tid + i * 256, n = v >> 3, kq = v & 7;                    \
            int nt = n >> 3, nn = n & 7;                                      \
            const float* pf = (const float*)&rb[i];                           \
            _Pragma("unroll")                                                 \
            for (int e = 0; e < 4; e++) {                                     \
                int kl = kq * 4 + e, ks = kl >> 3, kk = kl & 7;               \
                int ln = nn * 4 + (kk & 3);                                   \
                int r  = kk >> 2;                                             \
                Bf[((ks * 16 + nt) * 32 + ln) * 2 + r] = f2tf32(pf[e]);       \
            }                                                                 \
        }                                                                     \
    } while (0)

    float acc[2][8][4];
#pragma unroll
    for (int i = 0; i < 2; i++)
#pragma unroll
        for (int j = 0; j < 8; j++)
#pragma unroll
            for (int r = 0; r < 4; r++) acc[i][j][r] = 0.f;

    const int niter = K / 32;
    LDG_TILE(0);
    STS_TILE(gsm);

    for (int kt = 0; kt < niter; kt++) {
        __syncthreads();
        uint32_t* st = gsm + (kt & 1) * 8192;
        if (kt + 1 < niter) LDG_TILE((kt + 1) * 32);

        uint32_t* Af = st;
        uint32_t* Bf = st + 4096;
#pragma unroll
        for (int ks = 0; ks < 4; ks++) {
            uint4 av[2];
            uint2 bv[8];
#pragma unroll
            for (int i = 0; i < 2; i++)
                av[i] = *(const uint4*)&Af[((ks * 8 + mw * 2 + i) * 32 + lane) * 4];
#pragma unroll
            for (int j = 0; j < 8; j++)
                bv[j] = *(const uint2*)&Bf[((ks * 16 + nw * 8 + j) * 32 + lane) * 2];
#pragma unroll
            for (int i = 0; i < 2; i++)
#pragma unroll
                for (int j = 0; j < 8; j++)
                    mma_tf32(acc[i][j][0], acc[i][j][1], acc[i][j][2], acc[i][j][3],
                             av[i].x, av[i].y, av[i].z, av[i].w, bv[j].x, bv[j].y);
        }
        if (kt + 1 < niter) STS_TILE(gsm + ((kt + 1) & 1) * 8192);
    }

#pragma unroll
    for (int i = 0; i < 2; i++) {
#pragma unroll
        for (int j = 0; j < 8; j++) {
            int row = row0 + mw * 32 + i * 16 + (lane >> 2);
            int col = col0 + nw * 64 + j * 8 + (lane & 3) * 2;
            float bb0 = 0.f, bb1 = 0.f;
            if (bias1) { bb0 += bias1[col]; bb1 += bias1[col + 1]; }
            if (bias2) { bb0 += bias2[col]; bb1 += bias2[col + 1]; }
            int r0 = row, r1 = row + 8;
            if (perm == 1) {
                r0 = (r0 & (SS - 1)) * BB + (r0 >> 10);
                r1 = (r1 & (SS - 1)) * BB + (r1 >> 10);
            } else if (perm == 2) {
                r0 = (r0 & 31) * SS + (r0 >> 5);
                r1 = (r1 & 31) * SS + (r1 >> 5);
            }
            *(float2*)&C[(size_t)r0 * N + col] =
                make_float2(acc[i][j][0] + bb0, acc[i][j][1] + bb1);
            *(float2*)&C[(size_t)r1 * N + col] =
                make_float2(acc[i][j][2] + bb0, acc[i][j][3] + bb1);
        }
    }
#undef LDG_TILE
#undef STS_TILE
}

// ---------------------------------------------------------------------------
// Atomic grid barrier (startup only; graph-replay safe).
// ---------------------------------------------------------------------------
__device__ __forceinline__ void grid_barrier() {
    __syncthreads();
    if (threadIdx.x == 0) {
        unsigned int gen = *((volatile unsigned int*)&g_gen);
        __threadfence();
        if (atomicAdd(&g_arrive, 1u) == NBLK - 1) {
            g_arrive = 0;
            __threadfence();
            atomicAdd(&g_gen, 1u);
        } else {
            while (*((volatile unsigned int*)&g_gen) == gen) { }
        }
    }
    __syncthreads();
}

// ---------------------------------------------------------------------------
// Persistent tf32-MMA LSTM recurrence, v6: two interleaved half-batch chains.
// Chains A (b 0-15) and B (b 16-31) are independent; alternating A_t, B_t
// hides each chain's sync latency behind the other's compute. W_hh SMEM tile
// shared by both halves. Per half: gated wait (1 poller, nanosleep) ->
// cp.async double-buffered staging -> mma (N=16) -> k-reduce (separate SMEM
// region) -> elementwise (tid<128; cell state in regs) -> RED publish.
// ---------------------------------------------------------------------------
extern __shared__ float smem_dyn[];

__global__ void __launch_bounds__(NTHR, 1)
lstm_persistent(const float* __restrict__ W_hh) {
    uint32_t* Wf = (uint32_t*)smem_dyn;            // 32768 u32 (128 KB)
    float* slabs = smem_dyn + 32768;               // [2 buf][8 warp][32 row][HS2] = 12288 f
    float* red   = smem_dyn + 32768 + 12288;       // [8 warp][32 c][RS2] = 4608 f

    const int tid  = threadIdx.x;
    const int lane = tid & 31;
    const int wid  = tid >> 5;
    const int blk  = blockIdx.x;
    const int hb   = blk * 8;

    float* redw = red + wid * 32 * RS2;

    // --- one-time W fragment fill (tf32, canonical m16n8k8 A layout) ---
    for (int idx = tid; idx < 32768; idx += NTHR) {
        int r  = idx & 3;
        int L  = (idx >> 2) & 31;
        int ks = (idx >> 7) & 127;
        int mt = idx >> 14;
        int c  = mt * 16 + (L >> 2) + (r & 1) * 8;   // gate-col 0..31
        int k  = ks * 8 + (L & 3) + (r >> 1) * 4;
        int g  = c >> 3, hh = c & 7;
        Wf[idx] = f2tf32(W_hh[(size_t)(g * HH + hb + hh) * HH + k]);
    }

    // --- reset done counters, init hT buf0 of both halves ---
    for (int i = blk * NTHR + tid; i < 2 * SS; i += NBLK * NTHR)
        g_done2[i >> 10][i & (SS - 1)] = 0u;
    for (int i = blk * NTHR + tid; i < HH * NB2; i += NBLK * NTHR) {
        g_hT2[0][0][i] = 0.f;
        g_hT2[1][0][i] = 0.f;
    }
    grid_barrier();

    const int b_e  = (tid & 127) >> 3;   // 0..15 (within half)
    const int hh_e = tid & 7;            // 0..7
    float cst[2] = {0.f, 0.f};

    for (int t = 0; t < SS; t++) {
#pragma unroll
        for (int hf = 0; hf < 2; hf++) {
            const float* __restrict__ hsrc = g_hT2[hf][t & 1];
            float* __restrict__       hdst = g_hT2[hf][(t + 1) & 1];

            // xg prefetch (tid<128 only; before the wait)
            float xp[4];
            if (tid < 128) {
                size_t base = ((size_t)t * BB + hf * NB2 + b_e) * GG + hb + hh_e;
#pragma unroll
                for (int g = 0; g < 4; g++)
                    xp[g] = __ldcg(&g_xg[base + (size_t)g * HH]);
            }

            // low-traffic step wait (usually instant: published a half ago)
            if (t > 0) {
                if (tid == 0) {
                    while (*((volatile unsigned int*)&g_done2[hf][t - 1]) < NBLK)
                        __nanosleep(32);
                }
                __syncthreads();
            }

            float acc[2][2][4];
#pragma unroll
            for (int m = 0; m < 2; m++)
#pragma unroll
                for (int n = 0; n < 2; n++)
#pragma unroll
                    for (int r = 0; r < 4; r++) acc[m][n][r] = 0.f;

            // warp slab per chunk: 32 k-rows x 16 b = 128 float4 (4/lane)
#define ISSUE2(c)                                                             \
            do {                                                              \
                float* dst = slabs + ((((c) & 1) * 8 + wid) * 32) * HS2;      \
                const int base_row = ((c) * 32 + wid * 4) * 8;                \
                _Pragma("unroll")                                             \
                for (int q = 0; q < 4; q++) {                                 \
                    int s = lane + 32 * q;                                    \
                    int lr = s >> 2, c4 = s & 3;                              \
                    cpa16(dst + lr * HS2 + c4 * 4,                            \
                          &hsrc[(base_row + lr) * NB2 + c4 * 4]);             \
                }                                                             \
                cpa_commit();                                                 \
            } while (0)

            ISSUE2(0);
            ISSUE2(1);

#pragma unroll
            for (int c = 0; c < 4; c++) {
                if (c < 3) cpa_wait1(); else cpa_wait0();
                __syncwarp();
                const float* sl = slabs + (((c & 1) * 8 + wid) * 32) * HS2;
#pragma unroll
                for (int j = 0; j < 4; j++) {
                    const int ksg = c * 32 + wid * 4 + j;
                    uint4 A0 = *(const uint4*)&Wf[(0 * 128 + ksg) * 128 + lane * 4];
                    uint4 A1 = *(const uint4*)&Wf[(1 * 128 + ksg) * 128 + lane * 4];
                    const float* bp0 = &sl[(j * 8 + (lane & 3)) * HS2 + (lane >> 2)];
                    const float* bp1 = bp0 + 4 * HS2;
#pragma unroll
                    for (int ng = 0; ng < 2; ng++) {
                        uint32_t b0 = __float_as_uint(bp0[ng * 8]);
                        uint32_t b1 = __float_as_uint(bp1[ng * 8]);
                        mma_tf32(acc[0][ng][0], acc[0][ng][1], acc[0][ng][2], acc[0][ng][3],
                                 A0.x, A0.y, A0.z, A0.w, b0, b1);
                        mma_tf32(acc[1][ng][0], acc[1][ng][1], acc[1][ng][2], acc[1][ng][3],
                                 A1.x, A1.y, A1.z, A1.w, b0, b1);
                    }
                }
                if (c < 2) ISSUE2(c + 2);
            }
#undef ISSUE2

            // k-reduce into warp-private region (separate SMEM; no pre-sync)
#pragma unroll
            for (int mt = 0; mt < 2; mt++) {
#pragma unroll
                for (int ng = 0; ng < 2; ng++) {
                    int c0 = mt * 16 + (lane >> 2);
                    int b0 = ng * 8 + 2 * (lane & 3);
                    *(float2*)&redw[(c0)     * RS2 + b0] =
                        make_float2(acc[mt][ng][0], acc[mt][ng][1]);
                    *(float2*)&redw[(c0 + 8) * RS2 + b0] =
                        make_float2(acc[mt][ng][2], acc[mt][ng][3]);
                }
            }
            __syncthreads();   // all warps' red visible

            // elementwise: 128 cells (16 b x 8 h); cell state in regs
            if (tid < 128) {
                float gate[4];
#pragma unroll
                for (int g = 0; g < 4; g++) {
                    float s = xp[g];
#pragma unroll
                    for (int w = 0; w < 8; w++)
                        s += red[w * 32 * RS2 + (g * 8 + hh_e) * RS2 + b_e];
                    gate[g] = s;
                }
                float iv = 1.f / (1.f + __expf(-gate[0]));
                float fv = 1.f / (1.f + __expf(-gate[1]));
                float gv = tanhf(gate[2]);
                float ov = 1.f / (1.f + __expf(-gate[3]));
                cst[hf] = fv * cst[hf] + iv * gv;
                float hv = ov * tanhf(cst[hf]);
                hdst[(hb + hh_e) * NB2 + b_e] = __uint_as_float(f2tf32(hv));
                g_hs[((size_t)t * BB + hf * NB2 + b_e) * HH + hb + hh_e] = hv;
            }

            __syncthreads();   // hT slice fully written
            if (tid == 0) {
                __threadfence();
                atomicAdd(&g_done2[hf][t], 1u);
            }
        }
    }
}

// ---------------------------------------------------------------------------
// Launch
// ---------------------------------------------------------------------------
extern "C" void kernel_launch(void* const* d_in, const int* in_sizes, int n_in,
                              void* d_out, int out_size) {
    const float* x     = (const float*)d_in[0];
    const float* W_ih  = (const float*)d_in[1];
    const float* W_hh  = (const float*)d_in[2];
    const float* b_ih  = (const float*)d_in[3];
    const float* b_hh  = (const float*)d_in[4];
    const float* W_key = (const float*)d_in[5];
    const float* b_key = (const float*)d_in[6];
    const float* W_val = (const float*)d_in[7];
    const float* b_val = (const float*)d_in[8];
    float* out = (float*)d_out;

    float* xg_ptr = nullptr;
    float* hs_ptr = nullptr;
    cudaGetSymbolAddress((void**)&xg_ptr, g_xg);
    cudaGetSymbolAddress((void**)&hs_ptr, g_hs);

    const int M = BB * SS;   // 32768
    const int LSTM_SMEM = (32768 + 12288 + 4608) * 4;   // 198,656 B
    const int GEMM_SMEM = 16384 * 4;                    //  65,536 B

    cudaFuncSetAttribute(lstm_persistent,
                         cudaFuncAttributeMaxDynamicSharedMemorySize, LSTM_SMEM);
    cudaFuncSetAttribute(gemm_tf32,
                         cudaFuncAttributeMaxDynamicSharedMemorySize, GEMM_SMEM);

    // Phase A: xg[S][B][4H] = perm1( x @ W_ih^T + b_ih + b_hh )
    {
        dim3 grid(GG / 128, M / 128);
        gemm_tf32<<<grid, 256, GEMM_SMEM>>>(x, W_ih, b_ih, b_hh, xg_ptr, M, GG, EE, 1);
    }

    // Phase B: persistent tf32-MMA LSTM recurrence (single launch)
    lstm_persistent<<<NBLK, NTHR, LSTM_SMEM>>>(W_hh);

    // Phase C: keys / values; hs is [S][B][H] -> out rows permuted back (perm=2)
    {
        dim3 grid(DKV / 128, M / 128);
        gemm_tf32<<<grid, 256, GEMM_SMEM>>>(hs_ptr, W_key, b_key, nullptr, out, M, DKV, HH, 2);
        gemm_tf32<<<grid, 256, GEMM_SMEM>>>(hs_ptr, W_val, b_val, nullptr,
                                            out + (size_t)M * DKV, M, DKV, HH, 2);
    }
}

// round 13
// speedup vs baseline: 1.2928x; 1.2928x over previous
#include <cuda_runtime.h>
#include <cstddef>
#include <cstdint>

// Problem constants
#define BB 32
#define SS 1024
#define EE 512
#define HH 1024
#define GG 4096          // 4*H
#define DKV 512

#define NBLK 128         // persistent grid: 1 block/SM
#define NTHR 256

#define RSTRIDE 34       // k-reduce row stride (even -> float2 8B-aligned)
#define HSTRIDE 40       // hT slab row stride: bank = (8k+b)&31 conflict-free

// Scratch (device globals; no allocation allowed)
// g_xg layout: [S][B][4H]   (step-major; written by phase A with perm=1)
// g_hs layout: [S][B][H]    (step-major; phase C permutes output rows, perm=2)
__device__ __align__(16) float g_xg[(size_t)BB * SS * GG];
__device__ __align__(16) float g_hs[(size_t)BB * SS * HH];
__device__ __align__(16) float g_hT[2][HH * BB];             // ping-pong h^T [k][b], tf32-rounded
__device__ unsigned int g_done[SS];                          // per-step completion counters
__device__ unsigned int g_arrive = 0;
__device__ unsigned int g_gen = 0;

// ---------------------------------------------------------------------------
// helpers
// ---------------------------------------------------------------------------
__device__ __forceinline__ uint32_t f2tf32(float f) {
    uint32_t u;
    asm("cvt.rna.tf32.f32 %0, %1;" : "=r"(u) : "f"(f));
    return u;
}

__device__ __forceinline__ float tanh_fast(float x) {
    // 1 - 2/(e^{2x}+1), MUFU-based; |err| ~1e-6 relative
    return 1.f - 2.f / (__expf(2.f * x) + 1.f);
}

__device__ __forceinline__ void mma_tf32(float& d0, float& d1, float& d2, float& d3,
                                         uint32_t a0, uint32_t a1, uint32_t a2, uint32_t a3,
                                         uint32_t b0, uint32_t b1) {
    asm("mma.sync.aligned.m16n8k8.row.col.f32.tf32.tf32.f32 "
        "{%0,%1,%2,%3}, {%4,%5,%6,%7}, {%8,%9}, {%0,%1,%2,%3};"
        : "+f"(d0), "+f"(d1), "+f"(d2), "+f"(d3)
        : "r"(a0), "r"(a1), "r"(a2), "r"(a3), "r"(b0), "r"(b1));
}

__device__ __forceinline__ void cpa16(float* smem, const float* g) {
    uint32_t s = (uint32_t)__cvta_generic_to_shared(smem);
    asm volatile("cp.async.cg.shared.global [%0], [%1], 16;" :: "r"(s), "l"(g));
}
__device__ __forceinline__ void cpa_commit() {
    asm volatile("cp.async.commit_group;");
}
__device__ __forceinline__ void cpa_wait1() {
    asm volatile("cp.async.wait_group 1;");
}
__device__ __forceinline__ void cpa_wait0() {
    asm volatile("cp.async.wait_group 0;");
}

// ---------------------------------------------------------------------------
// tf32 tensor-core GEMM: C[M,N] = A[M,K]*W[N,K]^T + bias1 + bias2
// perm: 0 = identity; 1 = xg perm; 2 = out perm   (unchanged, passing)
// ---------------------------------------------------------------------------
__global__ void __launch_bounds__(256, 2)
gemm_tf32(const float* __restrict__ A,
          const float* __restrict__ W,
          const float* __restrict__ bias1,
          const float* __restrict__ bias2,
          float* __restrict__ C,
          int M, int N, int K, int perm) {
    extern __shared__ uint32_t gsm[];   // 2 stages x (Af 4096 + Bf 4096) u32

    const int tid  = threadIdx.x;
    const int lane = tid & 31;
    const int wid  = tid >> 5;
    const int mw   = wid >> 1;
    const int nw   = wid & 1;
    const int row0 = blockIdx.y * 128;
    const int col0 = blockIdx.x * 128;

    float4 ra[4], rb[4];

#define LDG_TILE(k0)                                                          \
    do {                                                                      \
        _Pragma("unroll")                                                     \
        for (int i = 0; i < 4; i++) {                                         \
            int v = tid + i * 256, row = v >> 3, kq = v & 7;                  \
            ra[i] = *(const float4*)&A[(size_t)(row0 + row) * K + (k0) + kq * 4]; \
        }                                                                     \
        _Pragma("unroll")                                                     \
        for (int i = 0; i < 4; i++) {                                         \
            int v = tid + i * 256, n = v >> 3, kq = v & 7;                    \
            rb[i] = *(const float4*)&W[(size_t)(col0 + n) * K + (k0) + kq * 4]; \
        }                                                                     \
    } while (0)

#define STS_TILE(stp)                                                         \
    do {                                                                      \
        uint32_t* Af = (stp);                                                 \
        uint32_t* Bf = (stp) + 4096;                                          \
        _Pragma("unroll")                                                     \
        for (int i = 0; i < 4; i++) {                                         \
            int v = tid + i * 256, row = v >> 3, kq = v & 7;                  \
            int mt = row >> 4, rw = row & 15;                                 \
            const float* pf = (const float*)&ra[i];                           \
            _Pragma("unroll")                                                 \
            for (int e = 0; e < 4; e++) {                                     \
                int kl = kq * 4 + e, ks = kl >> 3, kk = kl & 7;               \
                int ln = (rw & 7) * 4 + (kk & 3);                             \
                int r  = (rw >> 3) + 2 * (kk >> 2);                           \
                Af[((ks * 8 + mt) * 32 + ln) * 4 + r] = f2tf32(pf[e]);        \
            }                                                                 \
        }                                                                     \
        _Pragma("unroll")                                                     \
        for (int i = 0; i < 4; i++) {                                         \
            int v = tid + i * 256, n = v >> 3, kq = v & 7;                    \
            int nt = n >> 3, nn = n & 7;                                      \
            const float* pf = (const float*)&rb[i];                           \
            _Pragma("unroll")                                                 \
            for (int e = 0; e < 4; e++) {                                     \
                int kl = kq * 4 + e, ks = kl >> 3, kk = kl & 7;               \
                int ln = nn * 4 + (kk & 3);                                   \
                int r  = kk >> 2;                                             \
                Bf[((ks * 16 + nt) * 32 + ln) * 2 + r] = f2tf32(pf[e]);       \
            }                                                                 \
        }                                                                     \
    } while (0)

    float acc[2][8][4];
#pragma unroll
    for (int i = 0; i < 2; i++)
#pragma unroll
        for (int j = 0; j < 8; j++)
#pragma unroll
            for (int r = 0; r < 4; r++) acc[i][j][r] = 0.f;

    const int niter = K / 32;
    LDG_TILE(0);
    STS_TILE(gsm);

    for (int kt = 0; kt < niter; kt++) {
        __syncthreads();
        uint32_t* st = gsm + (kt & 1) * 8192;
        if (kt + 1 < niter) LDG_TILE((kt + 1) * 32);

        uint32_t* Af = st;
        uint32_t* Bf = st + 4096;
#pragma unroll
        for (int ks = 0; ks < 4; ks++) {
            uint4 av[2];
            uint2 bv[8];
#pragma unroll
            for (int i = 0; i < 2; i++)
                av[i] = *(const uint4*)&Af[((ks * 8 + mw * 2 + i) * 32 + lane) * 4];
#pragma unroll
            for (int j = 0; j < 8; j++)
                bv[j] = *(const uint2*)&Bf[((ks * 16 + nw * 8 + j) * 32 + lane) * 2];
#pragma unroll
            for (int i = 0; i < 2; i++)
#pragma unroll
                for (int j = 0; j < 8; j++)
                    mma_tf32(acc[i][j][0], acc[i][j][1], acc[i][j][2], acc[i][j][3],
                             av[i].x, av[i].y, av[i].z, av[i].w, bv[j].x, bv[j].y);
        }
        if (kt + 1 < niter) STS_TILE(gsm + ((kt + 1) & 1) * 8192);
    }

#pragma unroll
    for (int i = 0; i < 2; i++) {
#pragma unroll
        for (int j = 0; j < 8; j++) {
            int row = row0 + mw * 32 + i * 16 + (lane >> 2);
            int col = col0 + nw * 64 + j * 8 + (lane & 3) * 2;
            float bb0 = 0.f, bb1 = 0.f;
            if (bias1) { bb0 += bias1[col]; bb1 += bias1[col + 1]; }
            if (bias2) { bb0 += bias2[col]; bb1 += bias2[col + 1]; }
            int r0 = row, r1 = row + 8;
            if (perm == 1) {
                r0 = (r0 & (SS - 1)) * BB + (r0 >> 10);
                r1 = (r1 & (SS - 1)) * BB + (r1 >> 10);
            } else if (perm == 2) {
                r0 = (r0 & 31) * SS + (r0 >> 5);
                r1 = (r1 & 31) * SS + (r1 >> 5);
            }
            *(float2*)&C[(size_t)r0 * N + col] =
                make_float2(acc[i][j][0] + bb0, acc[i][j][1] + bb1);
            *(float2*)&C[(size_t)r1 * N + col] =
                make_float2(acc[i][j][2] + bb0, acc[i][j][3] + bb1);
        }
    }
#undef LDG_TILE
#undef STS_TILE
}

// ---------------------------------------------------------------------------
// Atomic grid barrier (startup only; graph-replay safe).
// ---------------------------------------------------------------------------
__device__ __forceinline__ void grid_barrier() {
    __syncthreads();
    if (threadIdx.x == 0) {
        unsigned int gen = *((volatile unsigned int*)&g_gen);
        __threadfence();
        if (atomicAdd(&g_arrive, 1u) == NBLK - 1) {
            g_arrive = 0;
            __threadfence();
            atomicAdd(&g_gen, 1u);
        } else {
            while (*((volatile unsigned int*)&g_gen) == gen) { }
        }
    }
    __syncthreads();
}

// ---------------------------------------------------------------------------
// Persistent tf32-MMA LSTM recurrence, v7 (= v5 + critical-path shavings).
// Block-wide step wait (ONE pure-spin poller/block), cp.async double-buffered
// hT staging, warp-private k-reduce, cell state in regs, fast tanh, and
// publish-before-hs-store (hs write overlaps the next step's wait).
// ---------------------------------------------------------------------------
extern __shared__ float smem_dyn[];

__global__ void __launch_bounds__(NTHR, 1)
lstm_persistent(const float* __restrict__ W_hh) {
    uint32_t* Wf = (uint32_t*)smem_dyn;        // 32768 u32 (128 KB)
    float* slabs = smem_dyn + 32768;           // [2 buf][8 warp][32 row][HSTRIDE]

    const int tid  = threadIdx.x;
    const int lane = tid & 31;
    const int wid  = tid >> 5;
    const int blk  = blockIdx.x;
    const int hb   = blk * 8;

    // warp-private reduce region: inside this warp's own buf0 slab
    float* redw = slabs + (wid * 32) * HSTRIDE;

    // --- one-time W fragment fill (tf32, canonical m16n8k8 A layout) ---
    for (int idx = tid; idx < 32768; idx += NTHR) {
        int r  = idx & 3;
        int L  = (idx >> 2) & 31;
        int ks = (idx >> 7) & 127;
        int mt = idx >> 14;
        int c  = mt * 16 + (L >> 2) + (r & 1) * 8;   // gate-col 0..31
        int k  = ks * 8 + (L & 3) + (r >> 1) * 4;
        int g  = c >> 3, hh = c & 7;
        Wf[idx] = f2tf32(W_hh[(size_t)(g * HH + hb + hh) * HH + k]);
    }

    // --- reset done counters, init hT[0]; startup barrier orders both ---
    for (int i = blk * NTHR + tid; i < SS; i += NBLK * NTHR)
        g_done[i] = 0u;
    for (int i = blk * NTHR + tid; i < HH * BB; i += NBLK * NTHR)
        g_hT[0][i] = 0.f;
    grid_barrier();

    const int b_e  = tid >> 3;      // 0..31
    const int hh_e = tid & 7;       // 0..7
    float cstate = 0.f;

    for (int t = 0; t < SS; t++) {
        const float* __restrict__ hsrc = g_hT[t & 1];

        // xg prefetch (independent of hT; issued before the wait)
        float xp[4];
        {
            size_t base = ((size_t)t * BB + b_e) * GG + hb + hh_e;
#pragma unroll
            for (int g = 0; g < 4; g++)
                xp[g] = __ldcg(&g_xg[base + (size_t)g * HH]);
        }

        // step wait: ONE pure-spin poller per block (128 chip-wide)
        if (t > 0) {
            if (tid == 0) {
                while (*((volatile unsigned int*)&g_done[t - 1]) < NBLK) { }
            }
            __syncthreads();
        }

        float acc[2][4][4];
#pragma unroll
        for (int m = 0; m < 2; m++)
#pragma unroll
            for (int n = 0; n < 4; n++)
#pragma unroll
                for (int r = 0; r < 4; r++) acc[m][n][r] = 0.f;

        // Slab per warp per chunk: 32 k-rows x 32 b = 256 float4.
#define ISSUE_CHUNK(c)                                                        \
        do {                                                                  \
            float* dst = slabs + ((((c) & 1) * 8 + wid) * 32) * HSTRIDE;      \
            const int base_row = ((c) * 32 + wid * 4) * 8;                    \
            _Pragma("unroll")                                                 \
            for (int q = 0; q < 8; q++) {                                     \
                int s = lane + 32 * q;                                        \
                int lr = s >> 3, c4 = s & 7;                                  \
                cpa16(dst + lr * HSTRIDE + c4 * 4,                            \
                      &hsrc[(base_row + lr) * BB + c4 * 4]);                  \
            }                                                                 \
            cpa_commit();                                                     \
        } while (0)

        ISSUE_CHUNK(0);
        ISSUE_CHUNK(1);

#pragma unroll
        for (int c = 0; c < 4; c++) {
            if (c < 3) cpa_wait1(); else cpa_wait0();
            __syncwarp();
            const float* sl = slabs + (((c & 1) * 8 + wid) * 32) * HSTRIDE;
#pragma unroll
            for (int j = 0; j < 4; j++) {
                const int ksg = c * 32 + wid * 4 + j;
                uint4 A0 = *(const uint4*)&Wf[(0 * 128 + ksg) * 128 + lane * 4];
                uint4 A1 = *(const uint4*)&Wf[(1 * 128 + ksg) * 128 + lane * 4];
                const float* bp0 = &sl[(j * 8 + (lane & 3)) * HSTRIDE + (lane >> 2)];
                const float* bp1 = bp0 + 4 * HSTRIDE;
#pragma unroll
                for (int ng = 0; ng < 4; ng++) {
                    uint32_t b0 = __float_as_uint(bp0[ng * 8]);
                    uint32_t b1 = __float_as_uint(bp1[ng * 8]);
                    mma_tf32(acc[0][ng][0], acc[0][ng][1], acc[0][ng][2], acc[0][ng][3],
                             A0.x, A0.y, A0.z, A0.w, b0, b1);
                    mma_tf32(acc[1][ng][0], acc[1][ng][1], acc[1][ng][2], acc[1][ng][3],
                             A1.x, A1.y, A1.z, A1.w, b0, b1);
                }
            }
            if (c < 2) ISSUE_CHUNK(c + 2);
        }
#undef ISSUE_CHUNK

        // k-reduce into warp-private region (own buf0 slab; no pre-sync needed)
#pragma unroll
        for (int mt = 0; mt < 2; mt++) {
#pragma unroll
            for (int ng = 0; ng < 4; ng++) {
                int c0 = mt * 16 + (lane >> 2);
                int b0 = ng * 8 + 2 * (lane & 3);
                *(float2*)&redw[(c0)     * RSTRIDE + b0] =
                    make_float2(acc[mt][ng][0], acc[mt][ng][1]);
                *(float2*)&redw[(c0 + 8) * RSTRIDE + b0] =
                    make_float2(acc[mt][ng][2], acc[mt][ng][3]);
            }
        }
        __syncthreads();   // all warps' red regions visible

        // elementwise update; hT write is the only publish-critical store
        float hv;
        {
            float gate[4];
#pragma unroll
            for (int g = 0; g < 4; g++) {
                float s = xp[g];
#pragma unroll
                for (int w = 0; w < 8; w++)
                    s += slabs[(w * 32) * HSTRIDE + (g * 8 + hh_e) * RSTRIDE + b_e];
                gate[g] = s;
            }
            float iv = 1.f / (1.f + __expf(-gate[0]));
            float fv = 1.f / (1.f + __expf(-gate[1]));
            float gv = tanh_fast(gate[2]);
            float ov = 1.f / (1.f + __expf(-gate[3]));
            cstate = fv * cstate + iv * gv;
            hv = ov * tanh_fast(cstate);
            g_hT[(t + 1) & 1][(hb + hh_e) * BB + b_e] = __uint_as_float(f2tf32(hv));
        }

        __syncthreads();   // hT slice fully written
        if (tid == 0) {
            __threadfence();
            atomicAdd(&g_done[t], 1u);   // RED publish (before hs store)
        }

        // hs store overlaps the next step's wait window
        g_hs[((size_t)t * BB + b_e) * HH + hb + hh_e] = hv;
    }
}

// ---------------------------------------------------------------------------
// Launch
// ---------------------------------------------------------------------------
extern "C" void kernel_launch(void* const* d_in, const int* in_sizes, int n_in,
                              void* d_out, int out_size) {
    const float* x     = (const float*)d_in[0];
    const float* W_ih  = (const float*)d_in[1];
    const float* W_hh  = (const float*)d_in[2];
    const float* b_ih  = (const float*)d_in[3];
    const float* b_hh  = (const float*)d_in[4];
    const float* W_key = (const float*)d_in[5];
    const float* b_key = (const float*)d_in[6];
    const float* W_val = (const float*)d_in[7];
    const float* b_val = (const float*)d_in[8];
    float* out = (float*)d_out;

    float* xg_ptr = nullptr;
    float* hs_ptr = nullptr;
    cudaGetSymbolAddress((void**)&xg_ptr, g_xg);
    cudaGetSymbolAddress((void**)&hs_ptr, g_hs);

    const int M = BB * SS;   // 32768
    const int LSTM_SMEM = (32768 + 2 * 8 * 32 * HSTRIDE) * 4;   // 212,992 B
    const int GEMM_SMEM = 16384 * 4;                            //  65,536 B

    cudaFuncSetAttribute(lstm_persistent,
                         cudaFuncAttributeMaxDynamicSharedMemorySize, LSTM_SMEM);
    cudaFuncSetAttribute(gemm_tf32,
                         cudaFuncAttributeMaxDynamicSharedMemorySize, GEMM_SMEM);

    // Phase A: xg[S][B][4H] = perm1( x @ W_ih^T + b_ih + b_hh )
    {
        dim3 grid(GG / 128, M / 128);
        gemm_tf32<<<grid, 256, GEMM_SMEM>>>(x, W_ih, b_ih, b_hh, xg_ptr, M, GG, EE, 1);
    }

    // Phase B: persistent tf32-MMA LSTM recurrence (single launch)
    lstm_persistent<<<NBLK, NTHR, LSTM_SMEM>>>(W_hh);

    // Phase C: keys / values; hs is [S][B][H] -> out rows permuted back (perm=2)
    {
        dim3 grid(DKV / 128, M / 128);
        gemm_tf32<<<grid, 256, GEMM_SMEM>>>(hs_ptr, W_key, b_key, nullptr, out, M, DKV, HH, 2);
        gemm_tf32<<<grid, 256, GEMM_SMEM>>>(hs_ptr, W_val, b_val, nullptr,
                                            out + (size_t)M * DKV, M, DKV, HH, 2);
    }
}

// round 14
// speedup vs baseline: 1.4343x; 1.1094x over previous
#include <cuda_runtime.h>
#include <cstddef>
#include <cstdint>

// Problem constants
#define BB 32
#define SS 1024
#define EE 512
#define HH 1024
#define GG 4096          // 4*H
#define DKV 512

#define NBLK 128         // persistent grid: 1 block/SM
#define NTHR 256

#define RSTRIDE 34       // k-reduce row stride (even -> float2 8B-aligned)
#define HSTRIDE 40       // hT slab row stride: bank = (8k+b)&31 conflict-free

#define SA 36            // gemm smem row stride (u32): STS.128 4wf, LDS.32 1wf

// Scratch (device globals; no allocation allowed)
// g_xg layout: [S][B][4H]   (step-major; written by phase A with perm=1)
// g_hs layout: [S][B][H]    (step-major; phase C permutes output rows, perm=2)
__device__ __align__(16) float g_xg[(size_t)BB * SS * GG];
__device__ __align__(16) float g_hs[(size_t)BB * SS * HH];
__device__ __align__(16) float g_hT[2][HH * BB];             // ping-pong h^T [k][b], tf32-rounded
__device__ unsigned int g_done[SS];                          // per-step completion counters
__device__ unsigned int g_arrive = 0;
__device__ unsigned int g_gen = 0;

// ---------------------------------------------------------------------------
// helpers
// ---------------------------------------------------------------------------
__device__ __forceinline__ uint32_t f2tf32(float f) {
    uint32_t u;
    asm("cvt.rna.tf32.f32 %0, %1;" : "=r"(u) : "f"(f));
    return u;
}

__device__ __forceinline__ void mma_tf32(float& d0, float& d1, float& d2, float& d3,
                                         uint32_t a0, uint32_t a1, uint32_t a2, uint32_t a3,
                                         uint32_t b0, uint32_t b1) {
    asm("mma.sync.aligned.m16n8k8.row.col.f32.tf32.tf32.f32 "
        "{%0,%1,%2,%3}, {%4,%5,%6,%7}, {%8,%9}, {%0,%1,%2,%3};"
        : "+f"(d0), "+f"(d1), "+f"(d2), "+f"(d3)
        : "r"(a0), "r"(a1), "r"(a2), "r"(a3), "r"(b0), "r"(b1));
}

__device__ __forceinline__ void cpa16(float* smem, const float* g) {
    uint32_t s = (uint32_t)__cvta_generic_to_shared(smem);
    asm volatile("cp.async.cg.shared.global [%0], [%1], 16;" :: "r"(s), "l"(g));
}
__device__ __forceinline__ void cpa_commit() {
    asm volatile("cp.async.commit_group;");
}
__device__ __forceinline__ void cpa_wait1() {
    asm volatile("cp.async.wait_group 1;");
}
__device__ __forceinline__ void cpa_wait0() {
    asm volatile("cp.async.wait_group 0;");
}

// ---------------------------------------------------------------------------
// tf32 tensor-core GEMM v2: C[M,N] = A[M,K]*W[N,K]^T + bias1 + bias2
// Row-major stride-SA smem tiles (tf32-converted at STS.128, bank-uniform),
// fragments gathered via conflict-free scalar LDS.32.
// perm: 0 = identity; 1 = xg perm; 2 = out perm
// ---------------------------------------------------------------------------
__global__ void __launch_bounds__(256, 2)
gemm_tf32(const float* __restrict__ A,
          const float* __restrict__ W,
          const float* __restrict__ bias1,
          const float* __restrict__ bias2,
          float* __restrict__ C,
          int M, int N, int K, int perm) {
    extern __shared__ uint32_t gsm[];   // 2 stages x (As 128*SA + Bs 128*SA)

    const int tid  = threadIdx.x;
    const int lane = tid & 31;
    const int wid  = tid >> 5;
    const int mw   = wid >> 1;          // 0..3 -> m-offset mw*32
    const int nw   = wid & 1;           // 0..1 -> n-offset nw*64
    const int row0 = blockIdx.y * 128;
    const int col0 = blockIdx.x * 128;

    const int STAGE = 2 * 128 * SA;     // u32 per stage (A tile + B tile)

    float4 ra[4], rb[4];

#define LDG_TILE(k0)                                                          \
    do {                                                                      \
        _Pragma("unroll")                                                     \
        for (int i = 0; i < 4; i++) {                                         \
            int v = tid + i * 256, row = v >> 3, kq = v & 7;                  \
            ra[i] = *(const float4*)&A[(size_t)(row0 + row) * K + (k0) + kq * 4]; \
        }                                                                     \
        _Pragma("unroll")                                                     \
        for (int i = 0; i < 4; i++) {                                         \
            int v = tid + i * 256, n = v >> 3, kq = v & 7;                    \
            rb[i] = *(const float4*)&W[(size_t)(col0 + n) * K + (k0) + kq * 4]; \
        }                                                                     \
    } while (0)

    // Row-major store: As[row*SA + k], Bs[row*SA + k]; tf32-convert, STS.128.
#define STS_TILE(stp)                                                         \
    do {                                                                      \
        uint32_t* As = (stp);                                                 \
        uint32_t* Bs = (stp) + 128 * SA;                                      \
        _Pragma("unroll")                                                     \
        for (int i = 0; i < 4; i++) {                                         \
            int v = tid + i * 256, row = v >> 3, kq = v & 7;                  \
            uint4 t;                                                          \
            t.x = f2tf32(ra[i].x); t.y = f2tf32(ra[i].y);                     \
            t.z = f2tf32(ra[i].z); t.w = f2tf32(ra[i].w);                     \
            *(uint4*)&As[row * SA + kq * 4] = t;                              \
        }                                                                     \
        _Pragma("unroll")                                                     \
        for (int i = 0; i < 4; i++) {                                         \
            int v = tid + i * 256, n = v >> 3, kq = v & 7;                    \
            uint4 t;                                                          \
            t.x = f2tf32(rb[i].x); t.y = f2tf32(rb[i].y);                     \
            t.z = f2tf32(rb[i].z); t.w = f2tf32(rb[i].w);                     \
            *(uint4*)&Bs[n * SA + kq * 4] = t;                                \
        }                                                                     \
    } while (0)

    float acc[2][8][4];
#pragma unroll
    for (int i = 0; i < 2; i++)
#pragma unroll
        for (int j = 0; j < 8; j++)
#pragma unroll
            for (int r = 0; r < 4; r++) acc[i][j][r] = 0.f;

    const int niter = K / 32;
    LDG_TILE(0);
    STS_TILE(gsm);

    // lane-fixed fragment gather bases
    const int lm = lane >> 2;           // 0..7
    const int lk = lane & 3;            // 0..3

    for (int kt = 0; kt < niter; kt++) {
        __syncthreads();
        uint32_t* st = gsm + (kt & 1) * STAGE;
        if (kt + 1 < niter) LDG_TILE((kt + 1) * 32);

        const uint32_t* As = st;
        const uint32_t* Bs = st + 128 * SA;
        // per-lane row bases
        const uint32_t* Abase = As + (mw * 32 + lm) * SA + lk;   // + i*16*SA, +8*SA, +ks*8, +4
        const uint32_t* Bbase = Bs + (nw * 64 + lm) * SA + lk;   // + j8*8*SA, +ks*8, +4

#pragma unroll
        for (int ks = 0; ks < 4; ks++) {
            uint32_t av[2][4];
#pragma unroll
            for (int i = 0; i < 2; i++) {
                const uint32_t* p = Abase + i * 16 * SA + ks * 8;
                av[i][0] = p[0];
                av[i][1] = p[8 * SA];
                av[i][2] = p[4];
                av[i][3] = p[8 * SA + 4];
            }
#pragma unroll
            for (int j = 0; j < 8; j++) {
                const uint32_t* q = Bbase + j * 8 * SA + ks * 8;
                uint32_t b0 = q[0];
                uint32_t b1 = q[4];
#pragma unroll
                for (int i = 0; i < 2; i++)
                    mma_tf32(acc[i][j][0], acc[i][j][1], acc[i][j][2], acc[i][j][3],
                             av[i][0], av[i][1], av[i][2], av[i][3], b0, b1);
            }
        }
        if (kt + 1 < niter) STS_TILE(gsm + ((kt + 1) & 1) * STAGE);
    }

    // epilogue (unchanged)
#pragma unroll
    for (int i = 0; i < 2; i++) {
#pragma unroll
        for (int j = 0; j < 8; j++) {
            int row = row0 + mw * 32 + i * 16 + (lane >> 2);
            int col = col0 + nw * 64 + j * 8 + (lane & 3) * 2;
            float bb0 = 0.f, bb1 = 0.f;
            if (bias1) { bb0 += bias1[col]; bb1 += bias1[col + 1]; }
            if (bias2) { bb0 += bias2[col]; bb1 += bias2[col + 1]; }
            int r0 = row, r1 = row + 8;
            if (perm == 1) {
                r0 = (r0 & (SS - 1)) * BB + (r0 >> 10);
                r1 = (r1 & (SS - 1)) * BB + (r1 >> 10);
            } else if (perm == 2) {
                r0 = (r0 & 31) * SS + (r0 >> 5);
                r1 = (r1 & 31) * SS + (r1 >> 5);
            }
            *(float2*)&C[(size_t)r0 * N + col] =
                make_float2(acc[i][j][0] + bb0, acc[i][j][1] + bb1);
            *(float2*)&C[(size_t)r1 * N + col] =
                make_float2(acc[i][j][2] + bb0, acc[i][j][3] + bb1);
        }
    }
#undef LDG_TILE
#undef STS_TILE
}

// ---------------------------------------------------------------------------
// Atomic grid barrier (startup only; graph-replay safe).
// ---------------------------------------------------------------------------
__device__ __forceinline__ void grid_barrier() {
    __syncthreads();
    if (threadIdx.x == 0) {
        unsigned int gen = *((volatile unsigned int*)&g_gen);
        __threadfence();
        if (atomicAdd(&g_arrive, 1u) == NBLK - 1) {
            g_arrive = 0;
            __threadfence();
            atomicAdd(&g_gen, 1u);
        } else {
            while (*((volatile unsigned int*)&g_gen) == gen) { }
        }
    }
    __syncthreads();
}

// ---------------------------------------------------------------------------
// Persistent tf32-MMA LSTM recurrence (v5 verbatim — best measured config).
// ---------------------------------------------------------------------------
extern __shared__ float smem_dyn[];

__global__ void __launch_bounds__(NTHR, 1)
lstm_persistent(const float* __restrict__ W_hh) {
    uint32_t* Wf = (uint32_t*)smem_dyn;        // 32768 u32 (128 KB)
    float* slabs = smem_dyn + 32768;           // [2 buf][8 warp][32 row][HSTRIDE]

    const int tid  = threadIdx.x;
    const int lane = tid & 31;
    const int wid  = tid >> 5;
    const int blk  = blockIdx.x;
    const int hb   = blk * 8;

    float* redw = slabs + (wid * 32) * HSTRIDE;

    for (int idx = tid; idx < 32768; idx += NTHR) {
        int r  = idx & 3;
        int L  = (idx >> 2) & 31;
        int ks = (idx >> 7) & 127;
        int mt = idx >> 14;
        int c  = mt * 16 + (L >> 2) + (r & 1) * 8;
        int k  = ks * 8 + (L & 3) + (r >> 1) * 4;
        int g  = c >> 3, hh = c & 7;
        Wf[idx] = f2tf32(W_hh[(size_t)(g * HH + hb + hh) * HH + k]);
    }

    for (int i = blk * NTHR + tid; i < SS; i += NBLK * NTHR)
        g_done[i] = 0u;
    for (int i = blk * NTHR + tid; i < HH * BB; i += NBLK * NTHR)
        g_hT[0][i] = 0.f;
    grid_barrier();

    const int b_e  = tid >> 3;
    const int hh_e = tid & 7;
    float cstate = 0.f;

    for (int t = 0; t < SS; t++) {
        const float* __restrict__ hsrc = g_hT[t & 1];

        float xp[4];
        {
            size_t base = ((size_t)t * BB + b_e) * GG + hb + hh_e;
#pragma unroll
            for (int g = 0; g < 4; g++)
                xp[g] = __ldcg(&g_xg[base + (size_t)g * HH]);
        }

        if (t > 0) {
            if (tid == 0) {
                while (*((volatile unsigned int*)&g_done[t - 1]) < NBLK)
                    __nanosleep(32);
            }
            __syncthreads();
        }

        float acc[2][4][4];
#pragma unroll
        for (int m = 0; m < 2; m++)
#pragma unroll
            for (int n = 0; n < 4; n++)
#pragma unroll
                for (int r = 0; r < 4; r++) acc[m][n][r] = 0.f;

#define ISSUE_CHUNK(c)                                                        \
        do {                                                                  \
            float* dst = slabs + ((((c) & 1) * 8 + wid) * 32) * HSTRIDE;      \
            const int base_row = ((c) * 32 + wid * 4) * 8;                    \
            _Pragma("unroll")                                                 \
            for (int q = 0; q < 8; q++) {                                     \
                int s = lane + 32 * q;                                        \
                int lr = s >> 3, c4 = s & 7;                                  \
                cpa16(dst + lr * HSTRIDE + c4 * 4,                            \
                      &hsrc[(base_row + lr) * BB + c4 * 4]);                  \
            }                                                                 \
            cpa_commit();                                                     \
        } while (0)

        ISSUE_CHUNK(0);
        ISSUE_CHUNK(1);

#pragma unroll
        for (int c = 0; c < 4; c++) {
            if (c < 3) cpa_wait1(); else cpa_wait0();
            __syncwarp();
            const float* sl = slabs + (((c & 1) * 8 + wid) * 32) * HSTRIDE;
#pragma unroll
            for (int j = 0; j < 4; j++) {
                const int ksg = c * 32 + wid * 4 + j;
                uint4 A0 = *(const uint4*)&Wf[(0 * 128 + ksg) * 128 + lane * 4];
                uint4 A1 = *(const uint4*)&Wf[(1 * 128 + ksg) * 128 + lane * 4];
                const float* bp0 = &sl[(j * 8 + (lane & 3)) * HSTRIDE + (lane >> 2)];
                const float* bp1 = bp0 + 4 * HSTRIDE;
#pragma unroll
                for (int ng = 0; ng < 4; ng++) {
                    uint32_t b0 = __float_as_uint(bp0[ng * 8]);
                    uint32_t b1 = __float_as_uint(bp1[ng * 8]);
                    mma_tf32(acc[0][ng][0], acc[0][ng][1], acc[0][ng][2], acc[0][ng][3],
                             A0.x, A0.y, A0.z, A0.w, b0, b1);
                    mma_tf32(acc[1][ng][0], acc[1][ng][1], acc[1][ng][2], acc[1][ng][3],
                             A1.x, A1.y, A1.z, A1.w, b0, b1);
                }
            }
            if (c < 2) ISSUE_CHUNK(c + 2);
        }
#undef ISSUE_CHUNK

#pragma unroll
        for (int mt = 0; mt < 2; mt++) {
#pragma unroll
            for (int ng = 0; ng < 4; ng++) {
                int c0 = mt * 16 + (lane >> 2);
                int b0 = ng * 8 + 2 * (lane & 3);
                *(float2*)&redw[(c0)     * RSTRIDE + b0] =
                    make_float2(acc[mt][ng][0], acc[mt][ng][1]);
                *(float2*)&redw[(c0 + 8) * RSTRIDE + b0] =
                    make_float2(acc[mt][ng][2], acc[mt][ng][3]);
            }
        }
        __syncthreads();

        {
            float gate[4];
#pragma unroll
            for (int g = 0; g < 4; g++) {
                float s = xp[g];
#pragma unroll
                for (int w = 0; w < 8; w++)
                    s += slabs[(w * 32) * HSTRIDE + (g * 8 + hh_e) * RSTRIDE + b_e];
                gate[g] = s;
            }
            float iv = 1.f / (1.f + __expf(-gate[0]));
            float fv = 1.f / (1.f + __expf(-gate[1]));
            float gv = tanhf(gate[2]);
            float ov = 1.f / (1.f + __expf(-gate[3]));
            cstate = fv * cstate + iv * gv;
            float hv = ov * tanhf(cstate);
            g_hT[(t + 1) & 1][(hb + hh_e) * BB + b_e] = __uint_as_float(f2tf32(hv));
            g_hs[((size_t)t * BB + b_e) * HH + hb + hh_e] = hv;
        }

        __syncthreads();
        if (tid == 0) {
            __threadfence();
            atomicAdd(&g_done[t], 1u);
        }
    }
}

// ---------------------------------------------------------------------------
// Launch
// ---------------------------------------------------------------------------
extern "C" void kernel_launch(void* const* d_in, const int* in_sizes, int n_in,
                              void* d_out, int out_size) {
    const float* x     = (const float*)d_in[0];
    const float* W_ih  = (const float*)d_in[1];
    const float* W_hh  = (const float*)d_in[2];
    const float* b_ih  = (const float*)d_in[3];
    const float* b_hh  = (const float*)d_in[4];
    const float* W_key = (const float*)d_in[5];
    const float* b_key = (const float*)d_in[6];
    const float* W_val = (const float*)d_in[7];
    const float* b_val = (const float*)d_in[8];
    float* out = (float*)d_out;

    float* xg_ptr = nullptr;
    float* hs_ptr = nullptr;
    cudaGetSymbolAddress((void**)&xg_ptr, g_xg);
    cudaGetSymbolAddress((void**)&hs_ptr, g_hs);

    const int M = BB * SS;   // 32768
    const int LSTM_SMEM = (32768 + 2 * 8 * 32 * HSTRIDE) * 4;   // 212,992 B
    const int GEMM_SMEM = 2 * 2 * 128 * SA * 4;                 //  73,728 B

    cudaFuncSetAttribute(lstm_persistent,
                         cudaFuncAttributeMaxDynamicSharedMemorySize, LSTM_SMEM);
    cudaFuncSetAttribute(gemm_tf32,
                         cudaFuncAttributeMaxDynamicSharedMemorySize, GEMM_SMEM);

    // Phase A: xg[S][B][4H] = perm1( x @ W_ih^T + b_ih + b_hh )
    {
        dim3 grid(GG / 128, M / 128);
        gemm_tf32<<<grid, 256, GEMM_SMEM>>>(x, W_ih, b_ih, b_hh, xg_ptr, M, GG, EE, 1);
    }

    // Phase B: persistent tf32-MMA LSTM recurrence (single launch)
    lstm_persistent<<<NBLK, NTHR, LSTM_SMEM>>>(W_hh);

    // Phase C: keys / values; hs is [S][B][H] -> out rows permuted back (perm=2)
    {
        dim3 grid(DKV / 128, M / 128);
        gemm_tf32<<<grid, 256, GEMM_SMEM>>>(hs_ptr, W_key, b_key, nullptr, out, M, DKV, HH, 2);
        gemm_tf32<<<grid, 256, GEMM_SMEM>>>(hs_ptr, W_val, b_val, nullptr,
                                            out + (size_t)M * DKV, M, DKV, HH, 2);
    }
}

// round 15
// speedup vs baseline: 1.4648x; 1.0213x over previous
#include <cuda_runtime.h>
#include <cstddef>
#include <cstdint>

// Problem constants
#define BB 32
#define SS 1024
#define EE 512
#define HH 1024
#define GG 4096          // 4*H
#define DKV 512

#define NBLK 128         // persistent grid: 1 block/SM
#define NTHR 256

#define RSTRIDE 34       // k-reduce row stride (even -> float2 8B-aligned)
#define HSTRIDE 40       // hT slab row stride: bank = (8k+b)&31 conflict-free

#define SA 36            // gemm smem row stride (u32): bank-uniform

// Scratch (device globals; no allocation allowed)
// g_xg layout: [S][B][4H]   (step-major; written by phase A with perm=1)
// g_hs layout: [S][B][H]    (step-major, tf32-rounded bits; phase C input)
__device__ __align__(16) float g_xg[(size_t)BB * SS * GG];
__device__ __align__(16) float g_hs[(size_t)BB * SS * HH];
__device__ __align__(16) float g_hT[2][HH * BB];             // ping-pong h^T [k][b], tf32-rounded
__device__ unsigned int g_done[SS];                          // per-step completion counters
__device__ unsigned int g_arrive = 0;
__device__ unsigned int g_gen = 0;

// pre-converted tf32 gemm inputs
__device__ __align__(16) uint32_t g_xt[(size_t)BB * SS * EE];   // x  (tf32 bits)
__device__ __align__(16) uint32_t g_wih[(size_t)GG * EE];       // W_ih
__device__ __align__(16) uint32_t g_wkey[(size_t)DKV * HH];     // W_key
__device__ __align__(16) uint32_t g_wval[(size_t)DKV * HH];     // W_val

// ---------------------------------------------------------------------------
// helpers
// ---------------------------------------------------------------------------
__device__ __forceinline__ uint32_t f2tf32(float f) {
    uint32_t u;
    asm("cvt.rna.tf32.f32 %0, %1;" : "=r"(u) : "f"(f));
    return u;
}

__device__ __forceinline__ void mma_tf32(float& d0, float& d1, float& d2, float& d3,
                                         uint32_t a0, uint32_t a1, uint32_t a2, uint32_t a3,
                                         uint32_t b0, uint32_t b1) {
    asm("mma.sync.aligned.m16n8k8.row.col.f32.tf32.tf32.f32 "
        "{%0,%1,%2,%3}, {%4,%5,%6,%7}, {%8,%9}, {%0,%1,%2,%3};"
        : "+f"(d0), "+f"(d1), "+f"(d2), "+f"(d3)
        : "r"(a0), "r"(a1), "r"(a2), "r"(a3), "r"(b0), "r"(b1));
}

__device__ __forceinline__ void cpa16(void* smem, const void* g) {
    uint32_t s = (uint32_t)__cvta_generic_to_shared(smem);
    asm volatile("cp.async.cg.shared.global [%0], [%1], 16;" :: "r"(s), "l"(g));
}
__device__ __forceinline__ void cpa_commit() {
    asm volatile("cp.async.commit_group;");
}
__device__ __forceinline__ void cpa_wait1() {
    asm volatile("cp.async.wait_group 1;");
}
__device__ __forceinline__ void cpa_wait0() {
    asm volatile("cp.async.wait_group 0;");
}

// ---------------------------------------------------------------------------
// elementwise fp32 -> tf32-bits pre-conversion
// ---------------------------------------------------------------------------
__global__ void cvt_tf32_kernel(const float* __restrict__ src,
                                uint32_t* __restrict__ dst, int n4) {
    int i = blockIdx.x * blockDim.x + threadIdx.x;
    if (i < n4) {
        float4 v = *(const float4*)&src[i * 4];
        uint4 t;
        t.x = f2tf32(v.x); t.y = f2tf32(v.y);
        t.z = f2tf32(v.z); t.w = f2tf32(v.w);
        *(uint4*)&dst[i * 4] = t;
    }
}

// ---------------------------------------------------------------------------
// tf32 tensor-core GEMM v3: inputs pre-converted to tf32 bits.
// cp.async tile staging straight into bank-uniform smem (no CVT/STS in loop),
// 1 syncthreads per kt, copy(kt+1) overlaps mma(kt).
// perm: 0 = identity; 1 = xg perm; 2 = out perm
// ---------------------------------------------------------------------------
__global__ void __launch_bounds__(256, 2)
gemm_tf32(const uint32_t* __restrict__ A,
          const uint32_t* __restrict__ W,
          const float* __restrict__ bias1,
          const float* __restrict__ bias2,
          float* __restrict__ C,
          int M, int N, int K, int perm) {
    extern __shared__ uint32_t gsm[];   // 2 stages x (As 128*SA + Bs 128*SA)

    const int tid  = threadIdx.x;
    const int lane = tid & 31;
    const int wid  = tid >> 5;
    const int mw   = wid >> 1;          // 0..3 -> m-offset mw*32
    const int nw   = wid & 1;           // 0..1 -> n-offset nw*64
    const int row0 = blockIdx.y * 128;
    const int col0 = blockIdx.x * 128;

    const int STAGE = 2 * 128 * SA;     // u32 per stage (A tile + B tile)

#define ISSUE_GT(kt)                                                          \
    do {                                                                      \
        uint32_t* As = gsm + ((kt) & 1) * STAGE;                              \
        uint32_t* Bs = As + 128 * SA;                                         \
        _Pragma("unroll")                                                     \
        for (int i = 0; i < 4; i++) {                                         \
            int v = tid + i * 256, row = v >> 3, kq = v & 7;                  \
            cpa16(&As[row * SA + kq * 4],                                     \
                  &A[(size_t)(row0 + row) * K + (kt) * 32 + kq * 4]);         \
        }                                                                     \
        _Pragma("unroll")                                                     \
        for (int i = 0; i < 4; i++) {                                         \
            int v = tid + i * 256, n = v >> 3, kq = v & 7;                    \
            cpa16(&Bs[n * SA + kq * 4],                                       \
                  &W[(size_t)(col0 + n) * K + (kt) * 32 + kq * 4]);           \
        }                                                                     \
        cpa_commit();                                                         \
    } while (0)

    float acc[2][8][4];
#pragma unroll
    for (int i = 0; i < 2; i++)
#pragma unroll
        for (int j = 0; j < 8; j++)
#pragma unroll
            for (int r = 0; r < 4; r++) acc[i][j][r] = 0.f;

    const int niter = K / 32;
    ISSUE_GT(0);

    const int lm = lane >> 2;           // 0..7
    const int lk = lane & 3;            // 0..3

    for (int kt = 0; kt < niter; kt++) {
        cpa_wait0();          // stage kt complete (only outstanding group)
        __syncthreads();      // visible to all; prior stage free
        if (kt + 1 < niter) ISSUE_GT(kt + 1);   // overlaps mma below

        const uint32_t* st = gsm + (kt & 1) * STAGE;
        const uint32_t* Abase = st + (mw * 32 + lm) * SA + lk;
        const uint32_t* Bbase = st + 128 * SA + (nw * 64 + lm) * SA + lk;

#pragma unroll
        for (int ks = 0; ks < 4; ks++) {
            uint32_t av[2][4];
#pragma unroll
            for (int i = 0; i < 2; i++) {
                const uint32_t* p = Abase + i * 16 * SA + ks * 8;
                av[i][0] = p[0];
                av[i][1] = p[8 * SA];
                av[i][2] = p[4];
                av[i][3] = p[8 * SA + 4];
            }
#pragma unroll
            for (int j = 0; j < 8; j++) {
                const uint32_t* q = Bbase + j * 8 * SA + ks * 8;
                uint32_t b0 = q[0];
                uint32_t b1 = q[4];
#pragma unroll
                for (int i = 0; i < 2; i++)
                    mma_tf32(acc[i][j][0], acc[i][j][1], acc[i][j][2], acc[i][j][3],
                             av[i][0], av[i][1], av[i][2], av[i][3], b0, b1);
            }
        }
    }

    // epilogue (unchanged)
#pragma unroll
    for (int i = 0; i < 2; i++) {
#pragma unroll
        for (int j = 0; j < 8; j++) {
            int row = row0 + mw * 32 + i * 16 + (lane >> 2);
            int col = col0 + nw * 64 + j * 8 + (lane & 3) * 2;
            float bb0 = 0.f, bb1 = 0.f;
            if (bias1) { bb0 += bias1[col]; bb1 += bias1[col + 1]; }
            if (bias2) { bb0 += bias2[col]; bb1 += bias2[col + 1]; }
            int r0 = row, r1 = row + 8;
            if (perm == 1) {
                r0 = (r0 & (SS - 1)) * BB + (r0 >> 10);
                r1 = (r1 & (SS - 1)) * BB + (r1 >> 10);
            } else if (perm == 2) {
                r0 = (r0 & 31) * SS + (r0 >> 5);
                r1 = (r1 & 31) * SS + (r1 >> 5);
            }
            *(float2*)&C[(size_t)r0 * N + col] =
                make_float2(acc[i][j][0] + bb0, acc[i][j][1] + bb1);
            *(float2*)&C[(size_t)r1 * N + col] =
                make_float2(acc[i][j][2] + bb0, acc[i][j][3] + bb1);
        }
    }
#undef ISSUE_GT
}

// ---------------------------------------------------------------------------
// Atomic grid barrier (startup only; graph-replay safe).
// ---------------------------------------------------------------------------
__device__ __forceinline__ void grid_barrier() {
    __syncthreads();
    if (threadIdx.x == 0) {
        unsigned int gen = *((volatile unsigned int*)&g_gen);
        __threadfence();
        if (atomicAdd(&g_arrive, 1u) == NBLK - 1) {
            g_arrive = 0;
            __threadfence();
            atomicAdd(&g_gen, 1u);
        } else {
            while (*((volatile unsigned int*)&g_gen) == gen) { }
        }
    }
    __syncthreads();
}

// ---------------------------------------------------------------------------
// Persistent tf32-MMA LSTM recurrence (v5 — best measured config).
// Only change: g_hs stores tf32-rounded bits (what the gemm rounded anyway).
// ---------------------------------------------------------------------------
extern __shared__ float smem_dyn[];

__global__ void __launch_bounds__(NTHR, 1)
lstm_persistent(const float* __restrict__ W_hh) {
    uint32_t* Wf = (uint32_t*)smem_dyn;        // 32768 u32 (128 KB)
    float* slabs = smem_dyn + 32768;           // [2 buf][8 warp][32 row][HSTRIDE]

    const int tid  = threadIdx.x;
    const int lane = tid & 31;
    const int wid  = tid >> 5;
    const int blk  = blockIdx.x;
    const int hb   = blk * 8;

    float* redw = slabs + (wid * 32) * HSTRIDE;

    for (int idx = tid; idx < 32768; idx += NTHR) {
        int r  = idx & 3;
        int L  = (idx >> 2) & 31;
        int ks = (idx >> 7) & 127;
        int mt = idx >> 14;
        int c  = mt * 16 + (L >> 2) + (r & 1) * 8;
        int k  = ks * 8 + (L & 3) + (r >> 1) * 4;
        int g  = c >> 3, hh = c & 7;
        Wf[idx] = f2tf32(W_hh[(size_t)(g * HH + hb + hh) * HH + k]);
    }

    for (int i = blk * NTHR + tid; i < SS; i += NBLK * NTHR)
        g_done[i] = 0u;
    for (int i = blk * NTHR + tid; i < HH * BB; i += NBLK * NTHR)
        g_hT[0][i] = 0.f;
    grid_barrier();

    const int b_e  = tid >> 3;
    const int hh_e = tid & 7;
    float cstate = 0.f;

    for (int t = 0; t < SS; t++) {
        const float* __restrict__ hsrc = g_hT[t & 1];

        float xp[4];
        {
            size_t base = ((size_t)t * BB + b_e) * GG + hb + hh_e;
#pragma unroll
            for (int g = 0; g < 4; g++)
                xp[g] = __ldcg(&g_xg[base + (size_t)g * HH]);
        }

        if (t > 0) {
            if (tid == 0) {
                while (*((volatile unsigned int*)&g_done[t - 1]) < NBLK)
                    __nanosleep(32);
            }
            __syncthreads();
        }

        float acc[2][4][4];
#pragma unroll
        for (int m = 0; m < 2; m++)
#pragma unroll
            for (int n = 0; n < 4; n++)
#pragma unroll
                for (int r = 0; r < 4; r++) acc[m][n][r] = 0.f;

#define ISSUE_CHUNK(c)                                                        \
        do {                                                                  \
            float* dst = slabs + ((((c) & 1) * 8 + wid) * 32) * HSTRIDE;      \
            const int base_row = ((c) * 32 + wid * 4) * 8;                    \
            _Pragma("unroll")                                                 \
            for (int q = 0; q < 8; q++) {                                     \
                int s = lane + 32 * q;                                        \
                int lr = s >> 3, c4 = s & 7;                                  \
                cpa16(dst + lr * HSTRIDE + c4 * 4,                            \
                      &hsrc[(base_row + lr) * BB + c4 * 4]);                  \
            }                                                                 \
            cpa_commit();                                                     \
        } while (0)

        ISSUE_CHUNK(0);
        ISSUE_CHUNK(1);

#pragma unroll
        for (int c = 0; c < 4; c++) {
            if (c < 3) cpa_wait1(); else cpa_wait0();
            __syncwarp();
            const float* sl = slabs + (((c & 1) * 8 + wid) * 32) * HSTRIDE;
#pragma unroll
            for (int j = 0; j < 4; j++) {
                const int ksg = c * 32 + wid * 4 + j;
                uint4 A0 = *(const uint4*)&Wf[(0 * 128 + ksg) * 128 + lane * 4];
                uint4 A1 = *(const uint4*)&Wf[(1 * 128 + ksg) * 128 + lane * 4];
                const float* bp0 = &sl[(j * 8 + (lane & 3)) * HSTRIDE + (lane >> 2)];
                const float* bp1 = bp0 + 4 * HSTRIDE;
#pragma unroll
                for (int ng = 0; ng < 4; ng++) {
                    uint32_t b0 = __float_as_uint(bp0[ng * 8]);
                    uint32_t b1 = __float_as_uint(bp1[ng * 8]);
                    mma_tf32(acc[0][ng][0], acc[0][ng][1], acc[0][ng][2], acc[0][ng][3],
                             A0.x, A0.y, A0.z, A0.w, b0, b1);
                    mma_tf32(acc[1][ng][0], acc[1][ng][1], acc[1][ng][2], acc[1][ng][3],
                             A1.x, A1.y, A1.z, A1.w, b0, b1);
                }
            }
            if (c < 2) ISSUE_CHUNK(c + 2);
        }
#undef ISSUE_CHUNK

#pragma unroll
        for (int mt = 0; mt < 2; mt++) {
#pragma unroll
            for (int ng = 0; ng < 4; ng++) {
                int c0 = mt * 16 + (lane >> 2);
                int b0 = ng * 8 + 2 * (lane & 3);
                *(float2*)&redw[(c0)     * RSTRIDE + b0] =
                    make_float2(acc[mt][ng][0], acc[mt][ng][1]);
                *(float2*)&redw[(c0 + 8) * RSTRIDE + b0] =
                    make_float2(acc[mt][ng][2], acc[mt][ng][3]);
            }
        }
        __syncthreads();

        {
            float gate[4];
#pragma unroll
            for (int g = 0; g < 4; g++) {
                float s = xp[g];
#pragma unroll
                for (int w = 0; w < 8; w++)
                    s += slabs[(w * 32) * HSTRIDE + (g * 8 + hh_e) * RSTRIDE + b_e];
                gate[g] = s;
            }
            float iv = 1.f / (1.f + __expf(-gate[0]));
            float fv = 1.f / (1.f + __expf(-gate[1]));
            float gv = tanhf(gate[2]);
            float ov = 1.f / (1.f + __expf(-gate[3]));
            cstate = fv * cstate + iv * gv;
            float hv = ov * tanhf(cstate);
            uint32_t hvt = f2tf32(hv);
            g_hT[(t + 1) & 1][(hb + hh_e) * BB + b_e] = __uint_as_float(hvt);
            g_hs[((size_t)t * BB + b_e) * HH + hb + hh_e] = __uint_as_float(hvt);
        }

        __syncthreads();
        if (tid == 0) {
            __threadfence();
            atomicAdd(&g_done[t], 1u);
        }
    }
}

// ---------------------------------------------------------------------------
// Launch
// ---------------------------------------------------------------------------
extern "C" void kernel_launch(void* const* d_in, const int* in_sizes, int n_in,
                              void* d_out, int out_size) {
    const float* x     = (const float*)d_in[0];
    const float* W_ih  = (const float*)d_in[1];
    const float* W_hh  = (const float*)d_in[2];
    const float* b_ih  = (const float*)d_in[3];
    const float* b_hh  = (const float*)d_in[4];
    const float* W_key = (const float*)d_in[5];
    const float* b_key = (const float*)d_in[6];
    const float* W_val = (const float*)d_in[7];
    const float* b_val = (const float*)d_in[8];
    float* out = (float*)d_out;

    float* xg_ptr = nullptr;
    float* hs_ptr = nullptr;
    uint32_t *xt_ptr = nullptr, *wih_ptr = nullptr, *wkey_ptr = nullptr, *wval_ptr = nullptr;
    cudaGetSymbolAddress((void**)&xg_ptr, g_xg);
    cudaGetSymbolAddress((void**)&hs_ptr, g_hs);
    cudaGetSymbolAddress((void**)&xt_ptr, g_xt);
    cudaGetSymbolAddress((void**)&wih_ptr, g_wih);
    cudaGetSymbolAddress((void**)&wkey_ptr, g_wkey);
    cudaGetSymbolAddress((void**)&wval_ptr, g_wval);

    const int M = BB * SS;   // 32768
    const int LSTM_SMEM = (32768 + 2 * 8 * 32 * HSTRIDE) * 4;   // 212,992 B
    const int GEMM_SMEM = 2 * 2 * 128 * SA * 4;                 //  73,728 B

    cudaFuncSetAttribute(lstm_persistent,
                         cudaFuncAttributeMaxDynamicSharedMemorySize, LSTM_SMEM);
    cudaFuncSetAttribute(gemm_tf32,
                         cudaFuncAttributeMaxDynamicSharedMemorySize, GEMM_SMEM);

    // Pre-convert gemm inputs to tf32 bits (bit-identical to in-loop cvt)
    {
        int n;
        n = BB * SS * EE / 4;
        cvt_tf32_kernel<<<(n + 255) / 256, 256>>>(x, xt_ptr, n);
        n = GG * EE / 4;
        cvt_tf32_kernel<<<(n + 255) / 256, 256>>>(W_ih, wih_ptr, n);
        n = DKV * HH / 4;
        cvt_tf32_kernel<<<(n + 255) / 256, 256>>>(W_key, wkey_ptr, n);
        cvt_tf32_kernel<<<(n + 255) / 256, 256>>>(W_val, wval_ptr, n);
    }

    // Phase A: xg[S][B][4H] = perm1( x @ W_ih^T + b_ih + b_hh )
    {
        dim3 grid(GG / 128, M / 128);
        gemm_tf32<<<grid, 256, GEMM_SMEM>>>(xt_ptr, wih_ptr, b_ih, b_hh, xg_ptr, M, GG, EE, 1);
    }

    // Phase B: persistent tf32-MMA LSTM recurrence (single launch)
    lstm_persistent<<<NBLK, NTHR, LSTM_SMEM>>>(W_hh);

    // Phase C: keys / values; hs holds tf32 bits -> out rows permuted (perm=2)
    {
        dim3 grid(DKV / 128, M / 128);
        gemm_tf32<<<grid, 256, GEMM_SMEM>>>((const uint32_t*)hs_ptr, wkey_ptr, b_key, nullptr,
                                            out, M, DKV, HH, 2);
        gemm_tf32<<<grid, 256, GEMM_SMEM>>>((const uint32_t*)hs_ptr, wval_ptr, b_val, nullptr,
                                            out + (size_t)M * DKV, M, DKV, HH, 2);
    }
}